// round 11
// baseline (speedup 1.0000x reference)
#include <cuda_runtime.h>

#define N_USERS 100000
#define M_ITEMS 200000
#define K_DIM   128
#define CAP     4096
#define SCAP    512
#define THREADS 256
#define GWARPS  8      // gather warps in finalize tail (THREADS/32)

// Compacted nonzeros + block-done counter. Zero-init at load; finalizer
// resets them so every graph replay starts clean (deterministic).
__device__ int          g_cnt;
__device__ unsigned int g_done;
__device__ int          g_idx[CAP];
__device__ float        g_val[CAP];

__global__ __launch_bounds__(THREADS, 4)
void fm_fused_kernel(const float* __restrict__ x,
                     const float* __restrict__ delta,
                     const float* __restrict__ w0,
                     const float* __restrict__ w_bias,
                     const float* __restrict__ uV,
                     const float* __restrict__ tV,
                     const float* __restrict__ bV,
                     float* __restrict__ out,
                     int nvec)
{
    const int tid = threadIdx.x;

    // Shared memory: 16B-aligned arrays FIRST (float4 access), scalars last.
    __shared__ __align__(16) float s_part[4][GWARPS][K_DIM];   // 16KB
    __shared__ __align__(16) int   sh_idx[SCAP];
    __shared__ __align__(16) float sh_val[SCAP];
    __shared__ float s_biasw[GWARPS];
    __shared__ float s_red[5][4];
    __shared__ bool  isLast;

    // ---------- Phase 1: scan my slice of x, compact nonzeros ----------
    int q = blockIdx.x * THREADS + tid;
    bool wrote = false;
    if (q < nvec) {
        uint4 v = reinterpret_cast<const uint4*>(x)[q];
        if (v.x | v.y | v.z | v.w) {
            unsigned int bits[4] = {v.x, v.y, v.z, v.w};
            #pragma unroll
            for (int j = 0; j < 4; j++) {
                if (bits[j] != 0u) {
                    int pos = atomicAdd(&g_cnt, 1);
                    if (pos < CAP) {
                        g_idx[pos] = q * 4 + j;
                        g_val[pos] = __uint_as_float(bits[j]);
                        wrote = true;
                    }
                }
            }
        }
    }
    if (wrote) __threadfence();   // only ~52 threads pay this

    // ---------- Phase 2: last-block-done election ----------
    __syncthreads();
    if (tid == 0) {
        __threadfence();
        unsigned int old = atomicAdd(&g_done, 1u);
        isLast = (old == gridDim.x - 1);
    }
    __syncthreads();
    if (!isLast) return;

    // ---------- Phase 3 (one block): gather rows, reduce, epilogue ----------
    __threadfence();  // acquire: observe all blocks' compaction writes

    int cnt = *(volatile int*)&g_cnt;
    if (cnt > CAP) cnt = CAP;
    const int c2 = cnt < SCAP ? cnt : SCAP;

    for (int j = tid; j < c2; j += THREADS) {
        sh_idx[j] = *(volatile int*)&g_idx[j];
        sh_val[j] = *(volatile float*)&g_val[j];
    }
    __syncthreads();

    const int warp = tid >> 5;
    const int lane = tid & 31;

    float4 au = {0,0,0,0}, at = {0,0,0,0}, as4 = {0,0,0,0}, aq = {0,0,0,0};
    float  ab = 0.f;

    // Batches of 8 rows per warp: all ~52 row gathers in flight in one round.
    for (int jb = warp; jb < cnt; jb += GWARPS * 8) {
        int   idx[8];
        float xv[8];
        bool  ok[8];
        #pragma unroll
        for (int c = 0; c < 8; c++) {
            int j = jb + GWARPS * c;
            ok[c] = (j < cnt);
            if (ok[c]) {
                if (j < SCAP) { idx[c] = sh_idx[j]; xv[c] = sh_val[j]; }
                else          { idx[c] = g_idx[j];  xv[c] = g_val[j];  }
            } else { idx[c] = 0; xv[c] = 0.f; }
        }

        float4 r[8];
        int    cls[8];
        float  wb[8];
        #pragma unroll
        for (int c = 0; c < 8; c++) {
            int i = idx[c];
            const float* rowbase;
            if (i < N_USERS)                { cls[c] = 0; rowbase = uV + (size_t)i * K_DIM; }
            else if (i < N_USERS + M_ITEMS) { cls[c] = 1; rowbase = tV + (size_t)(i - N_USERS) * K_DIM; }
            else                            { cls[c] = 2; rowbase = bV + (size_t)(i - N_USERS - M_ITEMS) * K_DIM; }
            r[c]  = reinterpret_cast<const float4*>(rowbase)[lane];
            wb[c] = (lane == 0 && ok[c]) ? w_bias[i] : 0.f;
        }

        #pragma unroll
        for (int c = 0; c < 8; c++) {
            if (!ok[c]) continue;
            float v = xv[c];
            ab += v * wb[c];
            if (cls[c] == 0) {
                au.x += v * r[c].x; au.y += v * r[c].y; au.z += v * r[c].z; au.w += v * r[c].w;
            } else if (cls[c] == 1) {
                at.x += v * r[c].x; at.y += v * r[c].y; at.z += v * r[c].z; at.w += v * r[c].w;
            } else {
                as4.x += v * r[c].x; as4.y += v * r[c].y; as4.z += v * r[c].z; as4.w += v * r[c].w;
                aq.x += v * r[c].x * r[c].x; aq.y += v * r[c].y * r[c].y;
                aq.z += v * r[c].z * r[c].z; aq.w += v * r[c].w * r[c].w;
            }
        }
    }

    *reinterpret_cast<float4*>(&s_part[0][warp][lane * 4]) = au;
    *reinterpret_cast<float4*>(&s_part[1][warp][lane * 4]) = at;
    *reinterpret_cast<float4*>(&s_part[2][warp][lane * 4]) = as4;
    *reinterpret_cast<float4*>(&s_part[3][warp][lane * 4]) = aq;
    if (lane == 0) s_biasw[warp] = ab;
    __syncthreads();

    if (tid < K_DIM) {
        float u = 0.f, t = 0.f, s = 0.f, sq = 0.f;
        #pragma unroll
        for (int w = 0; w < GWARPS; w++) {
            u  += s_part[0][w][tid];
            t  += s_part[1][w][tid];
            s  += s_part[2][w][tid];
            sq += s_part[3][w][tid];
        }
        float ut = u * t;
        float tb = t * s;
        float ub = u * s;
        float ss = s * s;
        #pragma unroll
        for (int off = 16; off > 0; off >>= 1) {
            ut += __shfl_down_sync(0xFFFFFFFFu, ut, off);
            tb += __shfl_down_sync(0xFFFFFFFFu, tb, off);
            ub += __shfl_down_sync(0xFFFFFFFFu, ub, off);
            ss += __shfl_down_sync(0xFFFFFFFFu, ss, off);
            sq += __shfl_down_sync(0xFFFFFFFFu, sq, off);
        }
        if (lane == 0) {
            int w = tid >> 5;
            s_red[0][w] = ut;
            s_red[1][w] = tb;
            s_red[2][w] = ub;
            s_red[3][w] = ss;
            s_red[4][w] = sq;
        }
    }
    __syncthreads();

    if (tid == 0) {
        float ut = s_red[0][0] + s_red[0][1] + s_red[0][2] + s_red[0][3];
        float tb = s_red[1][0] + s_red[1][1] + s_red[1][2] + s_red[1][3];
        float ub = s_red[2][0] + s_red[2][1] + s_red[2][2] + s_red[2][3];
        float ss = s_red[3][0] + s_red[3][1] + s_red[3][2] + s_red[3][3];
        float sq = s_red[4][0] + s_red[4][1] + s_red[4][2] + s_red[4][3];

        float bias = 0.f;
        #pragma unroll
        for (int w = 0; w < GWARPS; w++) bias += s_biasw[w];

        float bs = 0.5f * (ss - sq);
        float y  = w0[0] + bias + ut + tb + bs + ub;
        float z  = y * delta[0];
        // -log_sigmoid(z) = softplus(-z), stable
        float r  = (z >= 0.0f) ? log1pf(expf(-z)) : (-z + log1pf(expf(z)));
        out[0] = r;

        // restore invariants for next graph replay
        g_cnt  = 0;
        g_done = 0u;
    }
}

extern "C" void kernel_launch(void* const* d_in, const int* in_sizes, int n_in,
                              void* d_out, int out_size) {
    const float* x      = (const float*)d_in[0];
    const float* delta  = (const float*)d_in[1];
    // d_in[2] = pmi (unused by reference)
    const float* w0     = (const float*)d_in[3];
    const float* w_bias = (const float*)d_in[4];
    const float* uV     = (const float*)d_in[5];
    const float* tV     = (const float*)d_in[6];
    const float* bV     = (const float*)d_in[7];
    float* out = (float*)d_out;

    int p    = in_sizes[4];    // 500000
    int nvec = p / 4;          // uint4 count (p divisible by 4)

    int blocks = (nvec + THREADS - 1) / THREADS;   // 489

    fm_fused_kernel<<<blocks, THREADS>>>(x, delta, w0, w_bias, uV, tV, bV, out, nvec);
}